// round 1
// baseline (speedup 1.0000x reference)
#include <cuda_runtime.h>

#define B 16
#define NN 1024
#define NF 16
#define NHID 32
#define HEADS 4
#define NP 12
#define WT_STRIDE 1028   // 1028 % 32 == 4 -> conflict-free LDS.128 per 8-lane phase

// ---------------- scratch (device globals; no allocation allowed) ----------------
__device__ float    g_Wh[B*HEADS*NN*NHID];     // 8 MB  [b][h][n][k]
__device__ float    g_fsrc[B*HEADS*NN];
__device__ float    g_fdst[B*HEADS*NN];
__device__ unsigned g_mask[NN*NN/32];          // adj>0 packed bits, [i][jword]
__device__ float    g_h[B*NN*HEADS*NHID];      // 8 MB  [b][n][h*32+k]
__device__ float    g_Wh2[B*NN*NP];            // [b][n][p]
__device__ float    g_gsrc[B*NN];
__device__ float    g_gdst[B*NN];

// ---------------- K0: pack adjacency to bitmask ----------------
__global__ void k_mask(const int* __restrict__ adj) {
    int i = blockIdx.x;
    int j = threadIdx.x;
    unsigned bal = __ballot_sync(0xffffffffu, adj[i*NN + j] > 0);
    if ((j & 31) == 0) g_mask[i*32 + (j >> 5)] = bal;
}

// ---------------- K1: Wh = x@W per head, f_src/f_dst dots ----------------
__global__ void k_wh(const float* __restrict__ x, const float* __restrict__ W,
                     const float* __restrict__ a_src, const float* __restrict__ a_dst) {
    __shared__ float Ws[NF*NHID];
    __shared__ float as_s[NHID], ad_s[NHID];
    int bh = blockIdx.x;
    int b = bh >> 2, h = bh & 3;
    int tid = threadIdx.x;
    for (int i = tid; i < NF*NHID; i += 256) Ws[i] = W[h*NF*NHID + i];
    if (tid < NHID) { as_s[tid] = a_src[h*NHID + tid]; ad_s[tid] = a_dst[h*NHID + tid]; }
    __syncthreads();

    int n = blockIdx.y*256 + tid;
    const float4* xp = (const float4*)(x + ((size_t)b*NN + n)*NF);
    float xf[NF];
#pragma unroll
    for (int i = 0; i < NF/4; i++) {
        float4 v = __ldg(xp + i);
        xf[4*i] = v.x; xf[4*i+1] = v.y; xf[4*i+2] = v.z; xf[4*i+3] = v.w;
    }
    float wh[NHID];
#pragma unroll
    for (int k = 0; k < NHID; k++) wh[k] = 0.f;
#pragma unroll
    for (int f = 0; f < NF; f++) {
        float xv = xf[f];
#pragma unroll
        for (int k = 0; k < NHID; k++) wh[k] += xv * Ws[f*NHID + k];
    }
    float fs = 0.f, fd = 0.f;
#pragma unroll
    for (int k = 0; k < NHID; k++) { fs += wh[k]*as_s[k]; fd += wh[k]*ad_s[k]; }

    float* op = g_Wh + ((size_t)bh*NN + n)*NHID;
#pragma unroll
    for (int k = 0; k < NHID; k += 4)
        *(float4*)(op + k) = make_float4(wh[k], wh[k+1], wh[k+2], wh[k+3]);
    g_fsrc[bh*NN + n] = fs;
    g_fdst[bh*NN + n] = fd;
}

// ---------------- K2: fused masked softmax + attn@Wh + ELU (layer 1) ----------------
// CTA = (b,h,half of rows). smem: WhT[32][1028] + f_dst[1024] + per-warp p tile.
// Warp owns 8 rows; lane = output component k. No max-subtraction needed (|e|<~4).
__global__ void __launch_bounds__(512, 1) k_attn1() {
    extern __shared__ float sm[];
    float* WhT  = sm;                        // 32*1028
    float* fd_s = sm + 32*WT_STRIDE;         // 1024
    float* p_s  = fd_s + NN;                 // 16 warps * 256

    int bh   = blockIdx.x >> 1;
    int half = blockIdx.x & 1;
    int b = bh >> 2, h = bh & 3;
    int tid = threadIdx.x;

    const float* Whg = g_Wh + (size_t)bh*NN*NHID;
    for (int idx = tid; idx < NN*NHID; idx += 512) {
        int j = idx >> 5, k = idx & 31;
        WhT[k*WT_STRIDE + j] = Whg[idx];
    }
    for (int idx = tid; idx < NN; idx += 512) fd_s[idx] = g_fdst[bh*NN + idx];
    __syncthreads();

    int warp = tid >> 5, lane = tid & 31;
    int rl = lane & 7;        // row this lane produces p for
    int tq = lane >> 3;       // 0..3
    float* pw = p_s + warp*256;

#pragma unroll 1
    for (int pass = 0; pass < 4; pass++) {
        int row0 = half*512 + pass*128 + warp*8;
        float fs = g_fsrc[bh*NN + row0 + rl];
        const unsigned* mrow = g_mask + (size_t)(row0 + rl)*32;

        float acc[8];
#pragma unroll
        for (int r = 0; r < 8; r++) acc[r] = 0.f;
        float zp = 0.f;

#pragma unroll 1
        for (int jb = 0; jb < NN; jb += 32) {
            unsigned mw = __ldg(mrow + (jb >> 5));
            // produce p[t][r] tile: lane writes words lane+32c -> conflict-free STS
#pragma unroll
            for (int c = 0; c < 8; c++) {
                int t = tq + 4*c;
                float e = fs + fd_s[jb + t];
                e = e > 0.f ? e : 0.2f*e;
                float p = ((mw >> t) & 1u) ? __expf(e) : 0.f;
                zp += p;
                pw[t*8 + rl] = p;
            }
            float wh[32];
#pragma unroll
            for (int u = 0; u < 8; u++) {
                float4 v = *(const float4*)&WhT[lane*WT_STRIDE + jb + 4*u];
                wh[4*u] = v.x; wh[4*u+1] = v.y; wh[4*u+2] = v.z; wh[4*u+3] = v.w;
            }
            __syncwarp();
#pragma unroll
            for (int t = 0; t < 32; t++) {
                float wv = wh[t];
                float4 pA = *(const float4*)&pw[t*8];
                float4 pB = *(const float4*)&pw[t*8 + 4];
                acc[0] += pA.x*wv; acc[1] += pA.y*wv; acc[2] += pA.z*wv; acc[3] += pA.w*wv;
                acc[4] += pB.x*wv; acc[5] += pB.y*wv; acc[6] += pB.z*wv; acc[7] += pB.w*wv;
            }
            __syncwarp();
        }

        // Z per row: lanes {r, r+8, r+16, r+24} hold partials for row r
        zp += __shfl_xor_sync(0xffffffffu, zp, 8);
        zp += __shfl_xor_sync(0xffffffffu, zp, 16);
#pragma unroll
        for (int r = 0; r < 8; r++) {
            float Zr = __shfl_sync(0xffffffffu, zp, r);
            float v = acc[r] / Zr;
            v = v > 0.f ? v : (__expf(v) - 1.f);   // ELU
            g_h[((size_t)b*NN + row0 + r)*(HEADS*NHID) + h*NHID + lane] = v;
        }
    }
}

// ---------------- K3: Wh2 = h@W_out, g_src/g_dst dots ----------------
__global__ void k_wh2(const float* __restrict__ W_out,
                      const float* __restrict__ ao_src, const float* __restrict__ ao_dst) {
    __shared__ float Wo[128*NP];
    __shared__ float aos[NP], aod[NP];
    int tid = threadIdx.x;
    for (int i = tid; i < 128*NP; i += 256) Wo[i] = W_out[i];
    if (tid < NP) { aos[tid] = ao_src[tid]; aod[tid] = ao_dst[tid]; }
    __syncthreads();

    int bn = blockIdx.x*256 + tid;
    const float* hp = g_h + (size_t)bn*128;
    float o[NP];
#pragma unroll
    for (int p = 0; p < NP; p++) o[p] = 0.f;
    for (int d = 0; d < 128; d += 4) {
        float4 hv = *(const float4*)(hp + d);
        float hh[4] = {hv.x, hv.y, hv.z, hv.w};
#pragma unroll
        for (int q = 0; q < 4; q++) {
#pragma unroll
            for (int p = 0; p < NP; p++) o[p] += hh[q]*Wo[(d+q)*NP + p];
        }
    }
    float gs = 0.f, gd = 0.f;
#pragma unroll
    for (int p = 0; p < NP; p++) { gs += o[p]*aos[p]; gd += o[p]*aod[p]; }
    float* op = g_Wh2 + (size_t)bn*NP;
#pragma unroll
    for (int p = 0; p < NP; p++) op[p] = o[p];
    g_gsrc[bn] = gs;
    g_gdst[bn] = gd;
}

// ---------------- K4: fused masked softmax + attn2@Wh2 + ELU (layer 2) ----------------
__global__ void __launch_bounds__(512, 1) k_attn2(float* __restrict__ out) {
    extern __shared__ float sm[];
    float* Vs   = sm;           // 1024*12
    float* gd_s = sm + NN*NP;   // 1024
    int b = blockIdx.x >> 3;
    int chunk = blockIdx.x & 7;
    int tid = threadIdx.x;

    const float* Vg = g_Wh2 + (size_t)b*NN*NP;
    for (int i = tid; i < NN*NP; i += 512) Vs[i] = Vg[i];
    for (int i = tid; i < NN; i += 512) gd_s[i] = g_gdst[b*NN + i];
    __syncthreads();

    int warp = tid >> 5, lane = tid & 31;
#pragma unroll 1
    for (int rr = 0; rr < 8; rr++) {
        int i = chunk*128 + warp*8 + rr;
        float fs = g_gsrc[b*NN + i];
        const unsigned* mrow = g_mask + (size_t)i*32;
        float acc[NP];
#pragma unroll
        for (int p = 0; p < NP; p++) acc[p] = 0.f;
        float z = 0.f;

#pragma unroll 1
        for (int it = 0; it < 32; it++) {
            int j = it*32 + lane;
            unsigned mw = __ldg(mrow + it);
            float e = fs + gd_s[j];
            e = e > 0.f ? e : 0.2f*e;
            float p = ((mw >> lane) & 1u) ? __expf(e) : 0.f;
            z += p;
            const float* v = &Vs[j*NP];       // 48B rows -> 16B aligned
            float4 v0 = *(const float4*)v;
            float4 v1 = *(const float4*)(v + 4);
            float4 v2 = *(const float4*)(v + 8);
            acc[0] += p*v0.x; acc[1] += p*v0.y; acc[2]  += p*v0.z; acc[3]  += p*v0.w;
            acc[4] += p*v1.x; acc[5] += p*v1.y; acc[6]  += p*v1.z; acc[7]  += p*v1.w;
            acc[8] += p*v2.x; acc[9] += p*v2.y; acc[10] += p*v2.z; acc[11] += p*v2.w;
        }
#pragma unroll
        for (int s = 16; s > 0; s >>= 1) {
            z += __shfl_xor_sync(0xffffffffu, z, s);
#pragma unroll
            for (int p = 0; p < NP; p++)
                acc[p] += __shfl_xor_sync(0xffffffffu, acc[p], s);
        }
        if (lane == 0) {
            float inv = 1.f / z;
#pragma unroll
            for (int p = 0; p < NP; p++) {
                float v = acc[p]*inv;
                v = v > 0.f ? v : (__expf(v) - 1.f);   // outer ELU
                out[(size_t)b*NN*NP + (size_t)i*NP + p] = v;
            }
        }
    }
}

// ---------------- launch ----------------
extern "C" void kernel_launch(void* const* d_in, const int* in_sizes, int n_in,
                              void* d_out, int out_size) {
    const float* x         = (const float*)d_in[0];
    const int*   adj       = (const int*)  d_in[1];
    const float* W         = (const float*)d_in[2];
    const float* a_src     = (const float*)d_in[3];
    const float* a_dst     = (const float*)d_in[4];
    const float* W_out     = (const float*)d_in[5];
    const float* a_out_src = (const float*)d_in[6];
    const float* a_out_dst = (const float*)d_in[7];
    float* out = (float*)d_out;

    int smem2 = (32*WT_STRIDE + NN + 16*256) * (int)sizeof(float);  // ~152 KB
    int smem4 = (NN*NP + NN) * (int)sizeof(float);                  // ~52 KB
    cudaFuncSetAttribute(k_attn1, cudaFuncAttributeMaxDynamicSharedMemorySize, smem2);
    cudaFuncSetAttribute(k_attn2, cudaFuncAttributeMaxDynamicSharedMemorySize, smem4);

    k_mask<<<NN, NN>>>(adj);
    k_wh<<<dim3(B*HEADS, NN/256), 256>>>(x, W, a_src, a_dst);
    k_attn1<<<B*HEADS*2, 512, smem2>>>();
    k_wh2<<<B*NN/256, 256>>>(W_out, a_out_src, a_out_dst);
    k_attn2<<<B*8, 512, smem4>>>(out);
}